// round 1
// baseline (speedup 1.0000x reference)
#include <cuda_runtime.h>
#include <math.h>

// Problem constants
#define BB 2048      // batch
#define CC 50000     // classes
#define DD 128       // latent dim

static __device__ __constant__ float kS     = 20.0f;
static __device__ __constant__ float kCosM  = 0.9950041652780258f;   // cos(0.1)
static __device__ __constant__ float kSinM  = 0.09983341664682815f;  // sin(0.1)
static __device__ __constant__ float kEps   = 1e-7f;

// Scratch (device globals — no allocations allowed)
__device__ float g_inx[BB];     // 1/||x_b||
__device__ float g_inw[CC];     // 1/||W_c||
__device__ float g_S1[BB];      // sum exp(wf)         (softmax denominator)
__device__ float g_S2[BB];      // sum exp(S * logits') (CE denominator)
__device__ float g_mlab[BB];    // S * margined-cosine at label column

// ---------------------------------------------------------------------------
__global__ void k_zero() {
    int i = blockIdx.x * blockDim.x + threadIdx.x;
    if (i < BB) { g_S1[i] = 0.0f; g_S2[i] = 0.0f; }
}

// One warp per row; D=128 -> 4 floats per lane (float4)
__global__ void k_rownorm(const float* __restrict__ src, float* __restrict__ dst, int rows) {
    int gwarp = (blockIdx.x * blockDim.x + threadIdx.x) >> 5;
    int lane  = threadIdx.x & 31;
    if (gwarp >= rows) return;
    float4 v = reinterpret_cast<const float4*>(src + (size_t)gwarp * DD)[lane];
    float s = v.x*v.x + v.y*v.y + v.z*v.z + v.w*v.w;
    #pragma unroll
    for (int o = 16; o; o >>= 1) s += __shfl_xor_sync(0xffffffffu, s, o);
    if (lane == 0) dst[gwarp] = 1.0f / fmaxf(sqrtf(s), 1e-12f);
}

// ---------------------------------------------------------------------------
// GEMM + fused ArcFace epilogue.
// CTA tile: 64 batch-rows x 128 class-cols. 256 threads.
// warp w owns rows [w*8, w*8+8); lane owns cols {lane, lane+32, lane+64, lane+96}.
#define Bb 64
#define Bc 128
#define Bk 16

__global__ __launch_bounds__(256) void k_gemm(
    const float* __restrict__ X, const float* __restrict__ W,
    const float* __restrict__ bias, const int* __restrict__ labels,
    float* __restrict__ out)
{
    __shared__ float As[Bb][Bk + 1];
    __shared__ float Bs[Bc][Bk + 1];
    __shared__ int   sLab[Bb];

    const int tid  = threadIdx.x;
    const int warp = tid >> 5;
    const int lane = tid & 31;
    const int rowBase = blockIdx.y * Bb;
    const int colBase = blockIdx.x * Bc;

    if (tid < Bb) sLab[tid] = labels[rowBase + tid];

    float acc[8][4];
    #pragma unroll
    for (int i = 0; i < 8; i++)
        #pragma unroll
        for (int j = 0; j < 4; j++) acc[i][j] = 0.0f;

    for (int k0 = 0; k0 < DD; k0 += Bk) {
        // Load A tile: 64x16 floats = 1 float4/thread
        {
            int r  = tid >> 2;
            int kk = (tid & 3) << 2;
            float4 v = *reinterpret_cast<const float4*>(&X[(size_t)(rowBase + r) * DD + k0 + kk]);
            As[r][kk + 0] = v.x; As[r][kk + 1] = v.y; As[r][kk + 2] = v.z; As[r][kk + 3] = v.w;
        }
        // Load B tile: 128x16 floats = 2 float4/thread, guard c < CC
        #pragma unroll
        for (int s = 0; s < 2; s++) {
            int lin = tid + s * 256;            // 0..511
            int r   = lin >> 2;                 // 0..127
            int kk  = (lin & 3) << 2;
            int gc  = colBase + r;
            float4 v = make_float4(0.f, 0.f, 0.f, 0.f);
            if (gc < CC)
                v = *reinterpret_cast<const float4*>(&W[(size_t)gc * DD + k0 + kk]);
            Bs[r][kk + 0] = v.x; Bs[r][kk + 1] = v.y; Bs[r][kk + 2] = v.z; Bs[r][kk + 3] = v.w;
        }
        __syncthreads();

        #pragma unroll
        for (int kk = 0; kk < Bk; kk++) {
            float a[8], bb[4];
            #pragma unroll
            for (int i = 0; i < 8; i++) a[i] = As[warp * 8 + i][kk];
            #pragma unroll
            for (int j = 0; j < 4; j++) bb[j] = Bs[lane + 32 * j][kk];
            #pragma unroll
            for (int i = 0; i < 8; i++)
                #pragma unroll
                for (int j = 0; j < 4; j++)
                    acc[i][j] = fmaf(a[i], bb[j], acc[i][j]);
        }
        __syncthreads();
    }

    // Epilogue
    int   cc[4]; bool cok[4]; float inw[4], bc[4];
    #pragma unroll
    for (int j = 0; j < 4; j++) {
        cc[j]  = colBase + lane + 32 * j;
        cok[j] = (cc[j] < CC);
        inw[j] = cok[j] ? g_inw[cc[j]] : 0.0f;
        bc[j]  = cok[j] ? bias[cc[j]]  : 0.0f;
    }

    #pragma unroll
    for (int i = 0; i < 8; i++) {
        const int r   = rowBase + warp * 8 + i;
        const float ix = g_inx[r];
        const int lab  = sLab[warp * 8 + i];
        float s1 = 0.0f, s2 = 0.0f;
        #pragma unroll
        for (int j = 0; j < 4; j++) {
            if (!cok[j]) continue;
            float wf = fmaf(acc[i][j], ix * inw[j], bc[j]);
            float p  = __expf(wf);
            out[(size_t)r * CC + cc[j]] = p;   // unnormalized softmax numerator
            s1 += p;
            float lg;
            if (cc[j] == lab) {
                float t   = fminf(fmaxf(wf, -1.0f + kEps), 1.0f - kEps);
                float ctm = t * kCosM - sqrtf(fmaxf(1.0f - t * t, 0.0f)) * kSinM;
                lg = kS * ctm;
                g_mlab[r] = lg;                // written exactly once per row
            } else {
                lg = kS * wf;
            }
            s2 += __expf(lg);
        }
        #pragma unroll
        for (int o = 16; o; o >>= 1) {
            s1 += __shfl_xor_sync(0xffffffffu, s1, o);
            s2 += __shfl_xor_sync(0xffffffffu, s2, o);
        }
        if (lane == 0) {
            atomicAdd(&g_S1[r], s1);
            atomicAdd(&g_S2[r], s2);
        }
    }
}

// ---------------------------------------------------------------------------
// prediction[b,c] /= S1[b]   (float4 grid-stride)
__global__ void k_normalize(float* __restrict__ out) {
    const size_t total4 = (size_t)BB * CC / 4;     // CC % 4 == 0
    size_t i4 = (size_t)blockIdx.x * blockDim.x + threadIdx.x;
    if (i4 >= total4) return;
    int row = (int)(i4 / (CC / 4));
    float inv = 1.0f / g_S1[row];
    float4* p = reinterpret_cast<float4*>(out);
    float4 v = p[i4];
    v.x *= inv; v.y *= inv; v.z *= inv; v.w *= inv;
    p[i4] = v;
}

// loss = mean_b( log(S2[b]) - mlab[b] )
__global__ void k_loss(float* __restrict__ out, int out_size) {
    __shared__ float red[256];
    float s = 0.0f;
    for (int b = threadIdx.x; b < BB; b += 256)
        s += logf(g_S2[b]) - g_mlab[b];
    red[threadIdx.x] = s;
    __syncthreads();
    for (int o = 128; o; o >>= 1) {
        if (threadIdx.x < o) red[threadIdx.x] += red[threadIdx.x + o];
        __syncthreads();
    }
    if (threadIdx.x == 0) {
        float loss = red[0] / (float)BB;
        out[(size_t)BB * CC] = loss;           // flatten order: prediction, then loss
        if (out_size - 1 != (long long)BB * CC)
            out[out_size - 1] = loss;          // robustness to padding
    }
}

// ---------------------------------------------------------------------------
extern "C" void kernel_launch(void* const* d_in, const int* in_sizes, int n_in,
                              void* d_out, int out_size) {
    const float* x      = (const float*)d_in[0];   // [B, D]
    const float* W      = (const float*)d_in[1];   // [C, D]
    const float* bias   = (const float*)d_in[2];   // [C]
    const int*   labels = (const int*)  d_in[3];   // [B]
    float* out = (float*)d_out;

    float* d_inx; cudaGetSymbolAddress((void**)&d_inx, g_inx);
    float* d_inw; cudaGetSymbolAddress((void**)&d_inw, g_inw);

    k_zero<<<(BB + 255) / 256, 256>>>();
    k_rownorm<<<(BB + 7) / 8, 256>>>(x, d_inx, BB);
    k_rownorm<<<(CC + 7) / 8, 256>>>(W, d_inw, CC);

    dim3 grid((CC + Bc - 1) / Bc, BB / Bb);        // (391, 32)
    k_gemm<<<grid, 256>>>(x, W, bias, labels, out);

    size_t total4 = (size_t)BB * CC / 4;
    k_normalize<<<(unsigned)((total4 + 255) / 256), 256>>>(out);

    k_loss<<<1, 256>>>(out, out_size);
}

// round 3
// speedup vs baseline: 2.0207x; 2.0207x over previous
#include <cuda_runtime.h>
#include <cuda_bf16.h>
#include <math.h>
#include <stdint.h>

#define BB 2048      // batch
#define CC 50000     // classes
#define DD 128       // latent dim
#define CCP 50048    // padded classes = 391*128

#define TM 128
#define TN 128

static __device__ __constant__ float kCosM = 0.9950041652780258f;   // cos(0.1)
static __device__ __constant__ float kSinM = 0.09983341664682815f;  // sin(0.1)
static __device__ __constant__ float kEps  = 1e-7f;

// ---- scratch (device globals; no allocations allowed) ----
__device__ __align__(128) __nv_bfloat16 g_Xh[BB * DD];
__device__ __align__(128) __nv_bfloat16 g_Xl[BB * DD];
__device__ __align__(128) __nv_bfloat16 g_Wh[(size_t)CCP * DD];
__device__ __align__(128) __nv_bfloat16 g_Wl[(size_t)CCP * DD];
__device__ float g_S1[BB];    // sum exp(wf)
__device__ float g_S2[BB];    // sum exp(20*wf) (unmargined; corrected in k_loss)
__device__ float g_mlab[BB];  // 20 * margined cosine at label
__device__ float g_corr[BB];  // exp(20*margined) - exp(20*wf_label)

// ---------------------------------------------------------------------------
#define LDSM4(R, addr) \
    asm volatile("ldmatrix.sync.aligned.m8n8.x4.shared.b16 {%0,%1,%2,%3}, [%4];" \
        : "=r"((R)[0]), "=r"((R)[1]), "=r"((R)[2]), "=r"((R)[3]) : "r"(addr))

#define MMA16816(C, A, B) \
    asm volatile("mma.sync.aligned.m16n8k16.row.col.f32.bf16.bf16.f32 " \
        "{%0,%1,%2,%3}, {%4,%5,%6,%7}, {%8,%9}, {%0,%1,%2,%3};" \
        : "+f"((C)[0]), "+f"((C)[1]), "+f"((C)[2]), "+f"((C)[3]) \
        : "r"((A)[0]), "r"((A)[1]), "r"((A)[2]), "r"((A)[3]), \
          "r"((B)[0]), "r"((B)[1]))

__device__ __forceinline__ uint32_t smem_to_u32(const void* p) {
    uint32_t a;
    asm("{ .reg .u64 t; cvta.to.shared.u64 t, %1; cvt.u32.u64 %0, t; }" : "=r"(a) : "l"(p));
    return a;
}

__device__ __forceinline__ uint32_t pack2(__nv_bfloat16 a, __nv_bfloat16 b) {
    __nv_bfloat162 t; t.x = a; t.y = b;
    return *reinterpret_cast<uint32_t*>(&t);
}

__device__ __forceinline__ float pow20(float p) {
    float p2 = p * p, p4 = p2 * p2, p8 = p4 * p4, p16 = p8 * p8;
    return p16 * p4;
}

// ---------------------------------------------------------------------------
__global__ void k_zero() {
    int i = blockIdx.x * blockDim.x + threadIdx.x;
    if (i < BB) { g_S1[i] = 0.0f; g_S2[i] = 0.0f; }
}

// one warp per row: normalize + bf16 hi/lo split
__global__ void k_prep_x(const float* __restrict__ x) {
    int gw = (blockIdx.x * blockDim.x + threadIdx.x) >> 5;
    int lane = threadIdx.x & 31;
    if (gw >= BB) return;
    float4 v = reinterpret_cast<const float4*>(x + (size_t)gw * DD)[lane];
    float s = v.x*v.x + v.y*v.y + v.z*v.z + v.w*v.w;
    #pragma unroll
    for (int o = 16; o; o >>= 1) s += __shfl_xor_sync(0xffffffffu, s, o);
    float inv = 1.0f / fmaxf(sqrtf(s), 1e-12f);
    float a0 = v.x*inv, a1 = v.y*inv, a2 = v.z*inv, a3 = v.w*inv;
    __nv_bfloat16 h0 = __float2bfloat16(a0), h1 = __float2bfloat16(a1);
    __nv_bfloat16 h2 = __float2bfloat16(a2), h3 = __float2bfloat16(a3);
    __nv_bfloat16 l0 = __float2bfloat16(a0 - __bfloat162float(h0));
    __nv_bfloat16 l1 = __float2bfloat16(a1 - __bfloat162float(h1));
    __nv_bfloat16 l2 = __float2bfloat16(a2 - __bfloat162float(h2));
    __nv_bfloat16 l3 = __float2bfloat16(a3 - __bfloat162float(h3));
    reinterpret_cast<uint2*>(g_Xh + (size_t)gw * DD)[lane] = make_uint2(pack2(h0,h1), pack2(h2,h3));
    reinterpret_cast<uint2*>(g_Xl + (size_t)gw * DD)[lane] = make_uint2(pack2(l0,l1), pack2(l2,l3));
}

__global__ void k_prep_w(const float* __restrict__ W) {
    int gw = (blockIdx.x * blockDim.x + threadIdx.x) >> 5;
    int lane = threadIdx.x & 31;
    if (gw >= CCP) return;
    if (gw >= CC) {
        reinterpret_cast<uint2*>(g_Wh + (size_t)gw * DD)[lane] = make_uint2(0, 0);
        reinterpret_cast<uint2*>(g_Wl + (size_t)gw * DD)[lane] = make_uint2(0, 0);
        return;
    }
    float4 v = reinterpret_cast<const float4*>(W + (size_t)gw * DD)[lane];
    float s = v.x*v.x + v.y*v.y + v.z*v.z + v.w*v.w;
    #pragma unroll
    for (int o = 16; o; o >>= 1) s += __shfl_xor_sync(0xffffffffu, s, o);
    float inv = 1.0f / fmaxf(sqrtf(s), 1e-12f);
    float a0 = v.x*inv, a1 = v.y*inv, a2 = v.z*inv, a3 = v.w*inv;
    __nv_bfloat16 h0 = __float2bfloat16(a0), h1 = __float2bfloat16(a1);
    __nv_bfloat16 h2 = __float2bfloat16(a2), h3 = __float2bfloat16(a3);
    __nv_bfloat16 l0 = __float2bfloat16(a0 - __bfloat162float(h0));
    __nv_bfloat16 l1 = __float2bfloat16(a1 - __bfloat162float(h1));
    __nv_bfloat16 l2 = __float2bfloat16(a2 - __bfloat162float(h2));
    __nv_bfloat16 l3 = __float2bfloat16(a3 - __bfloat162float(h3));
    reinterpret_cast<uint2*>(g_Wh + (size_t)gw * DD)[lane] = make_uint2(pack2(h0,h1), pack2(h2,h3));
    reinterpret_cast<uint2*>(g_Wl + (size_t)gw * DD)[lane] = make_uint2(pack2(l0,l1), pack2(l2,l3));
}

// per-row label margin correction (exact fp32 recompute of label column)
__global__ void k_label(const float* __restrict__ x, const float* __restrict__ W,
                        const float* __restrict__ b, const int* __restrict__ labels) {
    int gw = (blockIdx.x * blockDim.x + threadIdx.x) >> 5;
    int lane = threadIdx.x & 31;
    if (gw >= BB) return;
    int lab = labels[gw];
    float4 xv = reinterpret_cast<const float4*>(x + (size_t)gw * DD)[lane];
    float4 wv = reinterpret_cast<const float4*>(W + (size_t)lab * DD)[lane];
    float sxx = xv.x*xv.x + xv.y*xv.y + xv.z*xv.z + xv.w*xv.w;
    float sww = wv.x*wv.x + wv.y*wv.y + wv.z*wv.z + wv.w*wv.w;
    float sxw = xv.x*wv.x + xv.y*wv.y + xv.z*wv.z + xv.w*wv.w;
    #pragma unroll
    for (int o = 16; o; o >>= 1) {
        sxx += __shfl_xor_sync(0xffffffffu, sxx, o);
        sww += __shfl_xor_sync(0xffffffffu, sww, o);
        sxw += __shfl_xor_sync(0xffffffffu, sxw, o);
    }
    if (lane == 0) {
        float wf = sxw / (fmaxf(sqrtf(sxx), 1e-12f) * fmaxf(sqrtf(sww), 1e-12f)) + b[lab];
        float t = fminf(fmaxf(wf, -1.0f + kEps), 1.0f - kEps);
        float ctm = t * kCosM - sqrtf(fmaxf(1.0f - t * t, 0.0f)) * kSinM;
        g_mlab[gw] = 20.0f * ctm;
        g_corr[gw] = __expf(20.0f * ctm) - __expf(20.0f * wf);
    }
}

// ---------------------------------------------------------------------------
// HMMA GEMM + fused ArcFace epilogue. CTA: 128 rows x 128 cols, K=128, 256 threads.
// 8 warps; warp tile 32(m) x 64(n). 3 passes: Xh*Wh, Xh*Wl, Xl*Wh.
// Smem tiles stored row-major [128][128] bf16 with 16B-chunk XOR swizzle
// (chunk' = chunk ^ (row & 7)) for conflict-free ldmatrix.
// ---------------------------------------------------------------------------
#define OFF_AH    0
#define OFF_AL    32768
#define OFF_BH    65536
#define OFF_BL    98304
#define OFF_BIAS  131072
#define OFF_S1    131584
#define OFF_S2    132096
#define SMEM_BYTES 132608

__device__ __forceinline__ void load_tile(const __nv_bfloat16* __restrict__ src,
                                          int rowBase, char* dst, int tid) {
    #pragma unroll
    for (int it = 0; it < 8; it++) {
        int idx = tid + it * 256;                // 0..2047
        int row = idx >> 4, ch = idx & 15;       // 16 chunks of 16B per row
        uint4 v = reinterpret_cast<const uint4*>(src + (size_t)(rowBase + row) * DD)[ch];
        int chs = ch ^ (row & 7);
        *reinterpret_cast<uint4*>(dst + row * 256 + chs * 16) = v;
    }
}

__global__ __launch_bounds__(256, 1) void k_gemm(const float* __restrict__ bias,
                                                 float* __restrict__ out) {
    extern __shared__ char smem[];
    const uint32_t sbase = smem_to_u32(smem);
    const int tid = threadIdx.x, wid = tid >> 5, lane = tid & 31;
    const int rowBase = blockIdx.y * TM, colBase = blockIdx.x * TN;
    const int wm = (wid & 3) * 32;      // warp row offset in tile
    const int wn = (wid >> 2) * 64;     // warp col offset in tile

    load_tile(g_Xh, rowBase, smem + OFF_AH, tid);
    load_tile(g_Xl, rowBase, smem + OFF_AL, tid);
    load_tile(g_Wh, colBase, smem + OFF_BH, tid);
    load_tile(g_Wl, colBase, smem + OFF_BL, tid);

    float* sBias = (float*)(smem + OFF_BIAS);
    float* sS1   = (float*)(smem + OFF_S1);
    float* sS2   = (float*)(smem + OFF_S2);
    if (tid < TM) {
        int c = colBase + tid;
        sBias[tid] = (c < CC) ? bias[c] : 0.0f;
        sS1[tid] = 0.0f; sS2[tid] = 0.0f;
    }
    __syncthreads();

    float c[2][8][4];
    #pragma unroll
    for (int mf = 0; mf < 2; mf++)
        #pragma unroll
        for (int nf = 0; nf < 8; nf++)
            #pragma unroll
            for (int e = 0; e < 4; e++) c[mf][nf][e] = 0.0f;

    const int g = lane >> 3;            // 0..3: ldmatrix sub-matrix group
    const int r = lane & 7;             // row within 8

    for (int pass = 0; pass < 3; pass++) {
        const uint32_t aOff = (pass == 2) ? OFF_AL : OFF_AH;
        const uint32_t bOff = (pass == 1) ? OFF_BL : OFF_BH;
        // A address row components (row & 7 == r for all)
        const uint32_t rowA = (uint32_t)(wm + (g & 1) * 8 + r);
        const uint32_t rowBq = (uint32_t)(wn + (g >> 1) * 8 + r);
        #pragma unroll
        for (int ks = 0; ks < 8; ks++) {
            uint32_t a[2][4];
            #pragma unroll
            for (int mf = 0; mf < 2; mf++) {
                uint32_t row = rowA + mf * 16;
                uint32_t chs = (uint32_t)((2 * ks + (g >> 1)) ^ r);
                LDSM4(a[mf], sbase + aOff + row * 256 + chs * 16);
            }
            uint32_t b[8][2];
            #pragma unroll
            for (int q = 0; q < 4; q++) {
                uint32_t row = rowBq + q * 16;
                uint32_t chs = (uint32_t)((2 * ks + (g & 1)) ^ r);
                uint32_t t4[4];
                LDSM4(t4, sbase + bOff + row * 256 + chs * 16);
                b[2*q][0] = t4[0]; b[2*q][1] = t4[1];
                b[2*q+1][0] = t4[2]; b[2*q+1][1] = t4[3];
            }
            #pragma unroll
            for (int mf = 0; mf < 2; mf++)
                #pragma unroll
                for (int nf = 0; nf < 8; nf++)
                    MMA16816(c[mf][nf], a[mf], b[nf]);
        }
    }

    // ---- fused epilogue: wf = acc + bias; p = exp(wf); store p; row sums ----
    const int qrow = lane >> 2, qcol = lane & 3;
    float s1a[2][2], s2a[2][2];
    #pragma unroll
    for (int mf = 0; mf < 2; mf++) { s1a[mf][0]=0.f; s1a[mf][1]=0.f; s2a[mf][0]=0.f; s2a[mf][1]=0.f; }

    #pragma unroll
    for (int mf = 0; mf < 2; mf++) {
        const int lr0 = wm + mf * 16 + qrow;
        const int lr1 = lr0 + 8;
        const size_t rb0 = (size_t)(rowBase + lr0) * CC;
        const size_t rb1 = (size_t)(rowBase + lr1) * CC;
        #pragma unroll
        for (int nf = 0; nf < 8; nf++) {
            const int lc = wn + nf * 8 + qcol * 2;
            const int gc = colBase + lc;
            if (gc < CC) {
                const float b0 = sBias[lc], b1 = sBias[lc + 1];
                float p0 = __expf(c[mf][nf][0] + b0);
                float p1 = __expf(c[mf][nf][1] + b1);
                *reinterpret_cast<float2*>(&out[rb0 + gc]) = make_float2(p0, p1);
                s1a[mf][0] += p0 + p1;
                s2a[mf][0] += pow20(p0) + pow20(p1);
                float p2 = __expf(c[mf][nf][2] + b0);
                float p3 = __expf(c[mf][nf][3] + b1);
                *reinterpret_cast<float2*>(&out[rb1 + gc]) = make_float2(p2, p3);
                s1a[mf][1] += p2 + p3;
                s2a[mf][1] += pow20(p2) + pow20(p3);
            }
        }
    }
    // quad reduce (lanes sharing a row differ only in qcol: xor 1, 2)
    #pragma unroll
    for (int o = 1; o <= 2; o <<= 1) {
        #pragma unroll
        for (int mf = 0; mf < 2; mf++) {
            s1a[mf][0] += __shfl_xor_sync(0xffffffffu, s1a[mf][0], o);
            s1a[mf][1] += __shfl_xor_sync(0xffffffffu, s1a[mf][1], o);
            s2a[mf][0] += __shfl_xor_sync(0xffffffffu, s2a[mf][0], o);
            s2a[mf][1] += __shfl_xor_sync(0xffffffffu, s2a[mf][1], o);
        }
    }
    if (qcol == 0) {
        #pragma unroll
        for (int mf = 0; mf < 2; mf++) {
            int lr0 = wm + mf * 16 + qrow;
            atomicAdd(&sS1[lr0], s1a[mf][0]);
            atomicAdd(&sS1[lr0 + 8], s1a[mf][1]);
            atomicAdd(&sS2[lr0], s2a[mf][0]);
            atomicAdd(&sS2[lr0 + 8], s2a[mf][1]);
        }
    }
    __syncthreads();
    if (tid < TM) {
        atomicAdd(&g_S1[rowBase + tid], sS1[tid]);
        atomicAdd(&g_S2[rowBase + tid], sS2[tid]);
    }
}

// ---------------------------------------------------------------------------
__global__ void k_normalize(float* __restrict__ out) {
    const size_t total4 = (size_t)BB * CC / 4;
    size_t i4 = (size_t)blockIdx.x * blockDim.x + threadIdx.x;
    if (i4 >= total4) return;
    int row = (int)(i4 / (CC / 4));
    float inv = 1.0f / g_S1[row];
    float4* p = reinterpret_cast<float4*>(out);
    float4 v = p[i4];
    v.x *= inv; v.y *= inv; v.z *= inv; v.w *= inv;
    p[i4] = v;
}

__global__ void k_loss(float* __restrict__ out, int out_size) {
    __shared__ float red[256];
    float s = 0.0f;
    for (int b = threadIdx.x; b < BB; b += 256)
        s += logf(g_S2[b] + g_corr[b]) - g_mlab[b];
    red[threadIdx.x] = s;
    __syncthreads();
    for (int o = 128; o; o >>= 1) {
        if (threadIdx.x < o) red[threadIdx.x] += red[threadIdx.x + o];
        __syncthreads();
    }
    if (threadIdx.x == 0) {
        float loss = red[0] / (float)BB;
        out[(size_t)BB * CC] = loss;
        if (out_size - 1 != (long long)BB * CC) out[out_size - 1] = loss;
    }
}

// ---------------------------------------------------------------------------
extern "C" void kernel_launch(void* const* d_in, const int* in_sizes, int n_in,
                              void* d_out, int out_size) {
    const float* x      = (const float*)d_in[0];
    const float* W      = (const float*)d_in[1];
    const float* bias   = (const float*)d_in[2];
    const int*   labels = (const int*)  d_in[3];
    float* out = (float*)d_out;

    static bool attr_set = false;
    if (!attr_set) {
        cudaFuncSetAttribute(k_gemm, cudaFuncAttributeMaxDynamicSharedMemorySize, SMEM_BYTES);
        attr_set = true;
    }

    k_zero<<<(BB + 255) / 256, 256>>>();
    k_prep_x<<<BB / 8, 256>>>(x);
    k_prep_w<<<CCP / 8, 256>>>(W);
    k_label<<<BB / 8, 256>>>(x, W, bias, labels);

    dim3 grid(CCP / TN, BB / TM);      // (391, 16)
    k_gemm<<<grid, 256, SMEM_BYTES>>>(bias, out);

    size_t total4 = (size_t)BB * CC / 4;
    k_normalize<<<(unsigned)((total4 + 255) / 256), 256>>>(out);

    k_loss<<<1, 256>>>(out, out_size);
}

// round 4
// speedup vs baseline: 3.4561x; 1.7104x over previous
#include <cuda_runtime.h>
#include <cuda_fp16.h>
#include <math.h>
#include <stdint.h>

#define BB 2048      // batch
#define CC 50000     // classes
#define DD 128       // latent dim
#define CCP 50048    // padded classes = 391*128

#define TM 128
#define TN 128

static __device__ __constant__ float kCosM = 0.9950041652780258f;   // cos(0.1)
static __device__ __constant__ float kSinM = 0.09983341664682815f;  // sin(0.1)
static __device__ __constant__ float kEps  = 1e-7f;

// ---- scratch (device globals; no allocations allowed) ----
__device__ __align__(128) __half g_Xh[BB * DD];
__device__ __align__(128) __half g_Wh[(size_t)CCP * DD];
__device__ __align__(128) __half g_P[(size_t)BB * CC];   // unnormalized exp(wf), fp16
__device__ float g_S1[BB];    // sum exp(wf)
__device__ float g_S2[BB];    // sum exp(20*wf) (unmargined; corrected in k_loss)
__device__ float g_mlab[BB];  // 20 * margined cosine at label
__device__ float g_corr[BB];  // exp(20*margined) - exp(20*wf_label)

// ---------------------------------------------------------------------------
#define LDSM4(R, addr) \
    asm volatile("ldmatrix.sync.aligned.m8n8.x4.shared.b16 {%0,%1,%2,%3}, [%4];" \
        : "=r"((R)[0]), "=r"((R)[1]), "=r"((R)[2]), "=r"((R)[3]) : "r"(addr))

#define MMA16816(C, A, B) \
    asm volatile("mma.sync.aligned.m16n8k16.row.col.f32.f16.f16.f32 " \
        "{%0,%1,%2,%3}, {%4,%5,%6,%7}, {%8,%9}, {%0,%1,%2,%3};" \
        : "+f"((C)[0]), "+f"((C)[1]), "+f"((C)[2]), "+f"((C)[3]) \
        : "r"((A)[0]), "r"((A)[1]), "r"((A)[2]), "r"((A)[3]), \
          "r"((B)[0]), "r"((B)[1]))

__device__ __forceinline__ uint32_t smem_to_u32(const void* p) {
    uint32_t a;
    asm("{ .reg .u64 t; cvta.to.shared.u64 t, %1; cvt.u32.u64 %0, t; }" : "=r"(a) : "l"(p));
    return a;
}

__device__ __forceinline__ float pow20(float p) {
    float p2 = p * p, p4 = p2 * p2, p8 = p4 * p4, p16 = p8 * p8;
    return p16 * p4;
}

// ---------------------------------------------------------------------------
__global__ void k_zero() {
    int i = blockIdx.x * blockDim.x + threadIdx.x;
    if (i < BB) { g_S1[i] = 0.0f; g_S2[i] = 0.0f; }
}

// one warp per row: fp32 normalize, convert to fp16
__global__ void k_prep_x(const float* __restrict__ x) {
    int gw = (blockIdx.x * blockDim.x + threadIdx.x) >> 5;
    int lane = threadIdx.x & 31;
    if (gw >= BB) return;
    float4 v = reinterpret_cast<const float4*>(x + (size_t)gw * DD)[lane];
    float s = v.x*v.x + v.y*v.y + v.z*v.z + v.w*v.w;
    #pragma unroll
    for (int o = 16; o; o >>= 1) s += __shfl_xor_sync(0xffffffffu, s, o);
    float inv = 1.0f / fmaxf(sqrtf(s), 1e-12f);
    __half2 h01 = __floats2half2_rn(v.x * inv, v.y * inv);
    __half2 h23 = __floats2half2_rn(v.z * inv, v.w * inv);
    reinterpret_cast<uint2*>(g_Xh + (size_t)gw * DD)[lane] =
        make_uint2(*reinterpret_cast<uint32_t*>(&h01), *reinterpret_cast<uint32_t*>(&h23));
}

__global__ void k_prep_w(const float* __restrict__ W) {
    int gw = (blockIdx.x * blockDim.x + threadIdx.x) >> 5;
    int lane = threadIdx.x & 31;
    if (gw >= CCP) return;
    if (gw >= CC) {
        reinterpret_cast<uint2*>(g_Wh + (size_t)gw * DD)[lane] = make_uint2(0, 0);
        return;
    }
    float4 v = reinterpret_cast<const float4*>(W + (size_t)gw * DD)[lane];
    float s = v.x*v.x + v.y*v.y + v.z*v.z + v.w*v.w;
    #pragma unroll
    for (int o = 16; o; o >>= 1) s += __shfl_xor_sync(0xffffffffu, s, o);
    float inv = 1.0f / fmaxf(sqrtf(s), 1e-12f);
    __half2 h01 = __floats2half2_rn(v.x * inv, v.y * inv);
    __half2 h23 = __floats2half2_rn(v.z * inv, v.w * inv);
    reinterpret_cast<uint2*>(g_Wh + (size_t)gw * DD)[lane] =
        make_uint2(*reinterpret_cast<uint32_t*>(&h01), *reinterpret_cast<uint32_t*>(&h23));
}

// per-row label margin correction (exact fp32 recompute of label column)
__global__ void k_label(const float* __restrict__ x, const float* __restrict__ W,
                        const float* __restrict__ b, const int* __restrict__ labels) {
    int gw = (blockIdx.x * blockDim.x + threadIdx.x) >> 5;
    int lane = threadIdx.x & 31;
    if (gw >= BB) return;
    int lab = labels[gw];
    float4 xv = reinterpret_cast<const float4*>(x + (size_t)gw * DD)[lane];
    float4 wv = reinterpret_cast<const float4*>(W + (size_t)lab * DD)[lane];
    float sxx = xv.x*xv.x + xv.y*xv.y + xv.z*xv.z + xv.w*xv.w;
    float sww = wv.x*wv.x + wv.y*wv.y + wv.z*wv.z + wv.w*wv.w;
    float sxw = xv.x*wv.x + xv.y*wv.y + xv.z*wv.z + xv.w*wv.w;
    #pragma unroll
    for (int o = 16; o; o >>= 1) {
        sxx += __shfl_xor_sync(0xffffffffu, sxx, o);
        sww += __shfl_xor_sync(0xffffffffu, sww, o);
        sxw += __shfl_xor_sync(0xffffffffu, sxw, o);
    }
    if (lane == 0) {
        float wf = sxw / (fmaxf(sqrtf(sxx), 1e-12f) * fmaxf(sqrtf(sww), 1e-12f)) + b[lab];
        float t = fminf(fmaxf(wf, -1.0f + kEps), 1.0f - kEps);
        float ctm = t * kCosM - sqrtf(fmaxf(1.0f - t * t, 0.0f)) * kSinM;
        g_mlab[gw] = 20.0f * ctm;
        g_corr[gw] = __expf(20.0f * ctm) - __expf(20.0f * wf);
    }
}

// ---------------------------------------------------------------------------
// Single-pass fp16 HMMA GEMM + fused ArcFace epilogue.
// CTA: 128x128, K=128 resident, 256 threads, 8 warps (warp tile 32x64).
// Smem row-major [128][128] half, 16B-chunk XOR swizzle (chunk ^= row&7).
// ---------------------------------------------------------------------------
#define OFF_AH    0
#define OFF_BH    32768
#define OFF_BIAS  65536
#define OFF_S1    66048
#define OFF_S2    66560
#define SMEM_BYTES 67072

__device__ __forceinline__ void load_tile(const __half* __restrict__ src,
                                          int rowBase, char* dst, int tid) {
    #pragma unroll
    for (int it = 0; it < 8; it++) {
        int idx = tid + it * 256;                // 0..2047
        int row = idx >> 4, ch = idx & 15;       // 16 chunks of 16B per row
        uint4 v = reinterpret_cast<const uint4*>(src + (size_t)(rowBase + row) * DD)[ch];
        int chs = ch ^ (row & 7);
        *reinterpret_cast<uint4*>(dst + row * 256 + chs * 16) = v;
    }
}

__global__ __launch_bounds__(256, 2) void k_gemm(const float* __restrict__ bias) {
    extern __shared__ char smem[];
    const uint32_t sbase = smem_to_u32(smem);
    const int tid = threadIdx.x, wid = tid >> 5, lane = tid & 31;
    const int rowBase = blockIdx.y * TM, colBase = blockIdx.x * TN;
    const int wm = (wid & 3) * 32;      // warp row offset in tile
    const int wn = (wid >> 2) * 64;     // warp col offset in tile

    load_tile(g_Xh, rowBase, smem + OFF_AH, tid);
    load_tile(g_Wh, colBase, smem + OFF_BH, tid);

    float* sBias = (float*)(smem + OFF_BIAS);
    float* sS1   = (float*)(smem + OFF_S1);
    float* sS2   = (float*)(smem + OFF_S2);
    if (tid < TM) {
        int c = colBase + tid;
        sBias[tid] = (c < CC) ? bias[c] : 0.0f;
        sS1[tid] = 0.0f; sS2[tid] = 0.0f;
    }
    __syncthreads();

    float c[2][8][4];
    #pragma unroll
    for (int mf = 0; mf < 2; mf++)
        #pragma unroll
        for (int nf = 0; nf < 8; nf++)
            #pragma unroll
            for (int e = 0; e < 4; e++) c[mf][nf][e] = 0.0f;

    const int g = lane >> 3;            // ldmatrix sub-matrix group
    const int r = lane & 7;
    const uint32_t rowA  = (uint32_t)(wm + (g & 1) * 8 + r);
    const uint32_t rowBq = (uint32_t)(wn + (g >> 1) * 8 + r);

    #pragma unroll
    for (int ks = 0; ks < 8; ks++) {
        uint32_t a[2][4];
        #pragma unroll
        for (int mf = 0; mf < 2; mf++) {
            uint32_t row = rowA + mf * 16;
            uint32_t chs = (uint32_t)((2 * ks + (g >> 1)) ^ r);
            LDSM4(a[mf], sbase + OFF_AH + row * 256 + chs * 16);
        }
        uint32_t b[8][2];
        #pragma unroll
        for (int q = 0; q < 4; q++) {
            uint32_t row = rowBq + q * 16;
            uint32_t chs = (uint32_t)((2 * ks + (g & 1)) ^ r);
            uint32_t t4[4];
            LDSM4(t4, sbase + OFF_BH + row * 256 + chs * 16);
            b[2*q][0] = t4[0]; b[2*q][1] = t4[1];
            b[2*q+1][0] = t4[2]; b[2*q+1][1] = t4[3];
        }
        #pragma unroll
        for (int mf = 0; mf < 2; mf++)
            #pragma unroll
            for (int nf = 0; nf < 8; nf++)
                MMA16816(c[mf][nf], a[mf], b[nf]);
    }

    // ---- fused epilogue: wf = acc + bias; p = exp(wf); store fp16 p; row sums ----
    const int qrow = lane >> 2, qcol = lane & 3;
    float s1a[2][2], s2a[2][2];
    #pragma unroll
    for (int mf = 0; mf < 2; mf++) { s1a[mf][0]=0.f; s1a[mf][1]=0.f; s2a[mf][0]=0.f; s2a[mf][1]=0.f; }

    #pragma unroll
    for (int mf = 0; mf < 2; mf++) {
        const int lr0 = wm + mf * 16 + qrow;
        const int lr1 = lr0 + 8;
        const size_t rb0 = (size_t)(rowBase + lr0) * CC;
        const size_t rb1 = (size_t)(rowBase + lr1) * CC;
        #pragma unroll
        for (int nf = 0; nf < 8; nf++) {
            const int lc = wn + nf * 8 + qcol * 2;
            const int gc = colBase + lc;
            if (gc < CC) {
                const float b0 = sBias[lc], b1 = sBias[lc + 1];
                float p0 = __expf(c[mf][nf][0] + b0);
                float p1 = __expf(c[mf][nf][1] + b1);
                __half2 h0 = __floats2half2_rn(p0, p1);
                *reinterpret_cast<__half2*>(&g_P[rb0 + gc]) = h0;
                s1a[mf][0] += p0 + p1;
                s2a[mf][0] += pow20(p0) + pow20(p1);
                float p2 = __expf(c[mf][nf][2] + b0);
                float p3 = __expf(c[mf][nf][3] + b1);
                __half2 h1 = __floats2half2_rn(p2, p3);
                *reinterpret_cast<__half2*>(&g_P[rb1 + gc]) = h1;
                s1a[mf][1] += p2 + p3;
                s2a[mf][1] += pow20(p2) + pow20(p3);
            }
        }
    }
    #pragma unroll
    for (int o = 1; o <= 2; o <<= 1) {
        #pragma unroll
        for (int mf = 0; mf < 2; mf++) {
            s1a[mf][0] += __shfl_xor_sync(0xffffffffu, s1a[mf][0], o);
            s1a[mf][1] += __shfl_xor_sync(0xffffffffu, s1a[mf][1], o);
            s2a[mf][0] += __shfl_xor_sync(0xffffffffu, s2a[mf][0], o);
            s2a[mf][1] += __shfl_xor_sync(0xffffffffu, s2a[mf][1], o);
        }
    }
    if (qcol == 0) {
        #pragma unroll
        for (int mf = 0; mf < 2; mf++) {
            int lr0 = wm + mf * 16 + qrow;
            atomicAdd(&sS1[lr0], s1a[mf][0]);
            atomicAdd(&sS1[lr0 + 8], s1a[mf][1]);
            atomicAdd(&sS2[lr0], s2a[mf][0]);
            atomicAdd(&sS2[lr0 + 8], s2a[mf][1]);
        }
    }
    __syncthreads();
    if (tid < TM) {
        atomicAdd(&g_S1[rowBase + tid], sS1[tid]);
        atomicAdd(&g_S2[rowBase + tid], sS2[tid]);
    }
}

// ---------------------------------------------------------------------------
// out[b,c] = fp32( g_P[b,c] ) / S1[b].  Grid: (ceil(CC/4/256), BB).
__global__ __launch_bounds__(256) void k_normalize(float* __restrict__ out) {
    const int row = blockIdx.y;
    const int c4 = blockIdx.x * 256 + threadIdx.x;       // float4 index within row
    if (c4 >= CC / 4) return;
    const float inv = 1.0f / g_S1[row];
    uint2 raw = *reinterpret_cast<const uint2*>(&g_P[(size_t)row * CC + c4 * 4]);
    __half2 h0 = *reinterpret_cast<__half2*>(&raw.x);
    __half2 h1 = *reinterpret_cast<__half2*>(&raw.y);
    float2 f0 = __half22float2(h0);
    float2 f1 = __half22float2(h1);
    float4 v = make_float4(f0.x * inv, f0.y * inv, f1.x * inv, f1.y * inv);
    *reinterpret_cast<float4*>(&out[(size_t)row * CC + c4 * 4]) = v;
}

__global__ void k_loss(float* __restrict__ out, int out_size) {
    __shared__ float red[256];
    float s = 0.0f;
    for (int b = threadIdx.x; b < BB; b += 256)
        s += logf(g_S2[b] + g_corr[b]) - g_mlab[b];
    red[threadIdx.x] = s;
    __syncthreads();
    for (int o = 128; o; o >>= 1) {
        if (threadIdx.x < o) red[threadIdx.x] += red[threadIdx.x + o];
        __syncthreads();
    }
    if (threadIdx.x == 0) {
        float loss = red[0] / (float)BB;
        out[(size_t)BB * CC] = loss;
        if (out_size - 1 != (long long)BB * CC) out[out_size - 1] = loss;
    }
}

// ---------------------------------------------------------------------------
extern "C" void kernel_launch(void* const* d_in, const int* in_sizes, int n_in,
                              void* d_out, int out_size) {
    const float* x      = (const float*)d_in[0];
    const float* W      = (const float*)d_in[1];
    const float* bias   = (const float*)d_in[2];
    const int*   labels = (const int*)  d_in[3];
    float* out = (float*)d_out;

    static bool attr_set = false;
    if (!attr_set) {
        cudaFuncSetAttribute(k_gemm, cudaFuncAttributeMaxDynamicSharedMemorySize, SMEM_BYTES);
        attr_set = true;
    }

    k_zero<<<(BB + 255) / 256, 256>>>();
    k_prep_x<<<BB / 8, 256>>>(x);
    k_prep_w<<<CCP / 8, 256>>>(W);
    k_label<<<BB / 8, 256>>>(x, W, bias, labels);

    dim3 grid(CCP / TN, BB / TM);      // (391, 16)
    k_gemm<<<grid, 256, SMEM_BYTES>>>(bias);

    dim3 ngrid((CC / 4 + 255) / 256, BB);   // (49, 2048)
    k_normalize<<<ngrid, 256>>>(out);

    k_loss<<<1, 256>>>(out, out_size);
}

// round 5
// speedup vs baseline: 3.5057x; 1.0144x over previous
#include <cuda_runtime.h>
#include <cuda_fp16.h>
#include <math.h>
#include <stdint.h>

#define BB 2048      // batch
#define CC 50000     // classes
#define DD 128       // latent dim
#define CCP 50048    // padded classes = 391*128

#define TM 128
#define TN 128

static __device__ __constant__ float kCosM = 0.9950041652780258f;   // cos(0.1)
static __device__ __constant__ float kSinM = 0.09983341664682815f;  // sin(0.1)
static __device__ __constant__ float kEps  = 1e-7f;

// ---- scratch (device globals; no allocations allowed) ----
__device__ __align__(128) __half g_Xh[BB * DD];
__device__ __align__(128) __half g_Wh[(size_t)CCP * DD];
__device__ float g_S1[BB];    // sum exp(wf)
__device__ float g_S2[BB];    // sum exp(20*wf) (unmargined; corrected in k_loss)
__device__ float g_mlab[BB];  // 20 * margined cosine at label
__device__ float g_corr[BB];  // exp(20*margined) - exp(20*wf_label)

// ---------------------------------------------------------------------------
#define LDSM4(R, addr) \
    asm volatile("ldmatrix.sync.aligned.m8n8.x4.shared.b16 {%0,%1,%2,%3}, [%4];" \
        : "=r"((R)[0]), "=r"((R)[1]), "=r"((R)[2]), "=r"((R)[3]) : "r"(addr))

#define MMA16816(C, A, B) \
    asm volatile("mma.sync.aligned.m16n8k16.row.col.f32.f16.f16.f32 " \
        "{%0,%1,%2,%3}, {%4,%5,%6,%7}, {%8,%9}, {%0,%1,%2,%3};" \
        : "+f"((C)[0]), "+f"((C)[1]), "+f"((C)[2]), "+f"((C)[3]) \
        : "r"((A)[0]), "r"((A)[1]), "r"((A)[2]), "r"((A)[3]), \
          "r"((B)[0]), "r"((B)[1]))

__device__ __forceinline__ uint32_t smem_to_u32(const void* p) {
    uint32_t a;
    asm("{ .reg .u64 t; cvta.to.shared.u64 t, %1; cvt.u32.u64 %0, t; }" : "=r"(a) : "l"(p));
    return a;
}

__device__ __forceinline__ float pow20(float p) {
    float p2 = p * p, p4 = p2 * p2, p8 = p4 * p4, p16 = p8 * p8;
    return p16 * p4;
}

// ---------------------------------------------------------------------------
__global__ void k_zero() {
    int i = blockIdx.x * blockDim.x + threadIdx.x;
    if (i < BB) { g_S1[i] = 0.0f; g_S2[i] = 0.0f; }
}

// one warp per row: fp32 normalize, convert to fp16
__global__ void k_prep_x(const float* __restrict__ x) {
    int gw = (blockIdx.x * blockDim.x + threadIdx.x) >> 5;
    int lane = threadIdx.x & 31;
    if (gw >= BB) return;
    float4 v = reinterpret_cast<const float4*>(x + (size_t)gw * DD)[lane];
    float s = v.x*v.x + v.y*v.y + v.z*v.z + v.w*v.w;
    #pragma unroll
    for (int o = 16; o; o >>= 1) s += __shfl_xor_sync(0xffffffffu, s, o);
    float inv = 1.0f / fmaxf(sqrtf(s), 1e-12f);
    __half2 h01 = __floats2half2_rn(v.x * inv, v.y * inv);
    __half2 h23 = __floats2half2_rn(v.z * inv, v.w * inv);
    reinterpret_cast<uint2*>(g_Xh + (size_t)gw * DD)[lane] =
        make_uint2(*reinterpret_cast<uint32_t*>(&h01), *reinterpret_cast<uint32_t*>(&h23));
}

__global__ void k_prep_w(const float* __restrict__ W) {
    int gw = (blockIdx.x * blockDim.x + threadIdx.x) >> 5;
    int lane = threadIdx.x & 31;
    if (gw >= CCP) return;
    if (gw >= CC) {
        reinterpret_cast<uint2*>(g_Wh + (size_t)gw * DD)[lane] = make_uint2(0, 0);
        return;
    }
    float4 v = reinterpret_cast<const float4*>(W + (size_t)gw * DD)[lane];
    float s = v.x*v.x + v.y*v.y + v.z*v.z + v.w*v.w;
    #pragma unroll
    for (int o = 16; o; o >>= 1) s += __shfl_xor_sync(0xffffffffu, s, o);
    float inv = 1.0f / fmaxf(sqrtf(s), 1e-12f);
    __half2 h01 = __floats2half2_rn(v.x * inv, v.y * inv);
    __half2 h23 = __floats2half2_rn(v.z * inv, v.w * inv);
    reinterpret_cast<uint2*>(g_Wh + (size_t)gw * DD)[lane] =
        make_uint2(*reinterpret_cast<uint32_t*>(&h01), *reinterpret_cast<uint32_t*>(&h23));
}

// per-row label margin correction (exact fp32 recompute of label column)
__global__ void k_label(const float* __restrict__ x, const float* __restrict__ W,
                        const float* __restrict__ b, const int* __restrict__ labels) {
    int gw = (blockIdx.x * blockDim.x + threadIdx.x) >> 5;
    int lane = threadIdx.x & 31;
    if (gw >= BB) return;
    int lab = labels[gw];
    float4 xv = reinterpret_cast<const float4*>(x + (size_t)gw * DD)[lane];
    float4 wv = reinterpret_cast<const float4*>(W + (size_t)lab * DD)[lane];
    float sxx = xv.x*xv.x + xv.y*xv.y + xv.z*xv.z + xv.w*xv.w;
    float sww = wv.x*wv.x + wv.y*wv.y + wv.z*wv.z + wv.w*wv.w;
    float sxw = xv.x*wv.x + xv.y*wv.y + xv.z*wv.z + xv.w*wv.w;
    #pragma unroll
    for (int o = 16; o; o >>= 1) {
        sxx += __shfl_xor_sync(0xffffffffu, sxx, o);
        sww += __shfl_xor_sync(0xffffffffu, sww, o);
        sxw += __shfl_xor_sync(0xffffffffu, sxw, o);
    }
    if (lane == 0) {
        float wf = sxw / (fmaxf(sqrtf(sxx), 1e-12f) * fmaxf(sqrtf(sww), 1e-12f)) + b[lab];
        float t = fminf(fmaxf(wf, -1.0f + kEps), 1.0f - kEps);
        float ctm = t * kCosM - sqrtf(fmaxf(1.0f - t * t, 0.0f)) * kSinM;
        g_mlab[gw] = 20.0f * ctm;
        g_corr[gw] = __expf(20.0f * ctm) - __expf(20.0f * wf);
    }
}

// ---------------------------------------------------------------------------
// Shared fp16 HMMA GEMM core. CTA: 128x128, K=128 resident, 256 threads,
// 8 warps (warp tile 32x64). Smem row-major [128][128] half,
// 16B-chunk XOR swizzle (chunk ^= row&7).
// ---------------------------------------------------------------------------
#define OFF_AH    0
#define OFF_BH    32768
#define OFF_BIAS  65536
#define OFF_S1    66048
#define OFF_S2    66560
#define SMEM_BYTES 67072

__device__ __forceinline__ void load_tile(const __half* __restrict__ src,
                                          int rowBase, char* dst, int tid) {
    #pragma unroll
    for (int it = 0; it < 8; it++) {
        int idx = tid + it * 256;                // 0..2047
        int row = idx >> 4, ch = idx & 15;       // 16 chunks of 16B per row
        uint4 v = reinterpret_cast<const uint4*>(src + (size_t)(rowBase + row) * DD)[ch];
        int chs = ch ^ (row & 7);
        *reinterpret_cast<uint4*>(dst + row * 256 + chs * 16) = v;
    }
}

__device__ __forceinline__ void gemm_core(uint32_t sbase, int wid, int lane,
                                          float c[2][8][4]) {
    #pragma unroll
    for (int mf = 0; mf < 2; mf++)
        #pragma unroll
        for (int nf = 0; nf < 8; nf++)
            #pragma unroll
            for (int e = 0; e < 4; e++) c[mf][nf][e] = 0.0f;

    const int wm = (wid & 3) * 32;
    const int wn = (wid >> 2) * 64;
    const int g = lane >> 3;
    const int r = lane & 7;
    const uint32_t rowA  = (uint32_t)(wm + (g & 1) * 8 + r);
    const uint32_t rowBq = (uint32_t)(wn + (g >> 1) * 8 + r);

    #pragma unroll
    for (int ks = 0; ks < 8; ks++) {
        uint32_t a[2][4];
        #pragma unroll
        for (int mf = 0; mf < 2; mf++) {
            uint32_t row = rowA + mf * 16;
            uint32_t chs = (uint32_t)((2 * ks + (g >> 1)) ^ r);
            LDSM4(a[mf], sbase + OFF_AH + row * 256 + chs * 16);
        }
        uint32_t b[8][2];
        #pragma unroll
        for (int q = 0; q < 4; q++) {
            uint32_t row = rowBq + q * 16;
            uint32_t chs = (uint32_t)((2 * ks + (g & 1)) ^ r);
            uint32_t t4[4];
            LDSM4(t4, sbase + OFF_BH + row * 256 + chs * 16);
            b[2*q][0] = t4[0]; b[2*q][1] = t4[1];
            b[2*q+1][0] = t4[2]; b[2*q+1][1] = t4[3];
        }
        #pragma unroll
        for (int mf = 0; mf < 2; mf++)
            #pragma unroll
            for (int nf = 0; nf < 8; nf++)
                MMA16816(c[mf][nf], a[mf], b[nf]);
    }
}

// ---------------------------------------------------------------------------
// Pass A: GEMM -> row sums S1 (softmax denom) and S2 (CE denom). No big stores.
__global__ __launch_bounds__(256, 2) void k_sums(const float* __restrict__ bias) {
    extern __shared__ char smem[];
    const uint32_t sbase = smem_to_u32(smem);
    const int tid = threadIdx.x, wid = tid >> 5, lane = tid & 31;
    const int rowBase = blockIdx.y * TM, colBase = blockIdx.x * TN;
    const int wm = (wid & 3) * 32;
    const int wn = (wid >> 2) * 64;

    load_tile(g_Xh, rowBase, smem + OFF_AH, tid);
    load_tile(g_Wh, colBase, smem + OFF_BH, tid);

    float* sBias = (float*)(smem + OFF_BIAS);
    float* sS1   = (float*)(smem + OFF_S1);
    float* sS2   = (float*)(smem + OFF_S2);
    if (tid < TM) {
        int cg = colBase + tid;
        sBias[tid] = (cg < CC) ? bias[cg] : 0.0f;
        sS1[tid] = 0.0f; sS2[tid] = 0.0f;
    }
    __syncthreads();

    float c[2][8][4];
    gemm_core(sbase, wid, lane, c);

    const int qrow = lane >> 2, qcol = lane & 3;
    float s1a[2][2], s2a[2][2];
    #pragma unroll
    for (int mf = 0; mf < 2; mf++) { s1a[mf][0]=0.f; s1a[mf][1]=0.f; s2a[mf][0]=0.f; s2a[mf][1]=0.f; }

    #pragma unroll
    for (int mf = 0; mf < 2; mf++) {
        #pragma unroll
        for (int nf = 0; nf < 8; nf++) {
            const int lc = wn + nf * 8 + qcol * 2;
            const int gc = colBase + lc;
            if (gc < CC) {
                const float b0 = sBias[lc], b1 = sBias[lc + 1];
                float p0 = __expf(c[mf][nf][0] + b0);
                float p1 = __expf(c[mf][nf][1] + b1);
                s1a[mf][0] += p0 + p1;
                s2a[mf][0] += pow20(p0) + pow20(p1);
                float p2 = __expf(c[mf][nf][2] + b0);
                float p3 = __expf(c[mf][nf][3] + b1);
                s1a[mf][1] += p2 + p3;
                s2a[mf][1] += pow20(p2) + pow20(p3);
            }
        }
    }
    #pragma unroll
    for (int o = 1; o <= 2; o <<= 1) {
        #pragma unroll
        for (int mf = 0; mf < 2; mf++) {
            s1a[mf][0] += __shfl_xor_sync(0xffffffffu, s1a[mf][0], o);
            s1a[mf][1] += __shfl_xor_sync(0xffffffffu, s1a[mf][1], o);
            s2a[mf][0] += __shfl_xor_sync(0xffffffffu, s2a[mf][0], o);
            s2a[mf][1] += __shfl_xor_sync(0xffffffffu, s2a[mf][1], o);
        }
    }
    if (qcol == 0) {
        #pragma unroll
        for (int mf = 0; mf < 2; mf++) {
            int lr0 = wm + mf * 16 + qrow;
            atomicAdd(&sS1[lr0], s1a[mf][0]);
            atomicAdd(&sS1[lr0 + 8], s1a[mf][1]);
            atomicAdd(&sS2[lr0], s2a[mf][0]);
            atomicAdd(&sS2[lr0 + 8], s2a[mf][1]);
        }
    }
    __syncthreads();
    if (tid < TM) {
        atomicAdd(&g_S1[rowBase + tid], sS1[tid]);
        atomicAdd(&g_S2[rowBase + tid], sS2[tid]);
    }
}

// ---------------------------------------------------------------------------
// Pass B: recompute GEMM, write final normalized fp32 predictions directly.
__global__ __launch_bounds__(256, 2) void k_write(const float* __restrict__ bias,
                                                  float* __restrict__ out) {
    extern __shared__ char smem[];
    const uint32_t sbase = smem_to_u32(smem);
    const int tid = threadIdx.x, wid = tid >> 5, lane = tid & 31;
    const int rowBase = blockIdx.y * TM, colBase = blockIdx.x * TN;
    const int wm = (wid & 3) * 32;
    const int wn = (wid >> 2) * 64;

    load_tile(g_Xh, rowBase, smem + OFF_AH, tid);
    load_tile(g_Wh, colBase, smem + OFF_BH, tid);

    float* sBias = (float*)(smem + OFF_BIAS);
    float* sInv  = (float*)(smem + OFF_S1);
    if (tid < TM) {
        int cg = colBase + tid;
        sBias[tid] = (cg < CC) ? bias[cg] : 0.0f;
        sInv[tid] = 1.0f / g_S1[rowBase + tid];
    }
    __syncthreads();

    float c[2][8][4];
    gemm_core(sbase, wid, lane, c);

    const int qrow = lane >> 2, qcol = lane & 3;
    #pragma unroll
    for (int mf = 0; mf < 2; mf++) {
        const int lr0 = wm + mf * 16 + qrow;
        const int lr1 = lr0 + 8;
        const float i0 = sInv[lr0], i1 = sInv[lr1];
        const size_t rb0 = (size_t)(rowBase + lr0) * CC;
        const size_t rb1 = (size_t)(rowBase + lr1) * CC;
        #pragma unroll
        for (int nf = 0; nf < 8; nf++) {
            const int lc = wn + nf * 8 + qcol * 2;
            const int gc = colBase + lc;
            if (gc < CC) {
                const float b0 = sBias[lc], b1 = sBias[lc + 1];
                float p0 = __expf(c[mf][nf][0] + b0) * i0;
                float p1 = __expf(c[mf][nf][1] + b1) * i0;
                *reinterpret_cast<float2*>(&out[rb0 + gc]) = make_float2(p0, p1);
                float p2 = __expf(c[mf][nf][2] + b0) * i1;
                float p3 = __expf(c[mf][nf][3] + b1) * i1;
                *reinterpret_cast<float2*>(&out[rb1 + gc]) = make_float2(p2, p3);
            }
        }
    }
}

// ---------------------------------------------------------------------------
__global__ void k_loss(float* __restrict__ out, int out_size) {
    __shared__ float red[256];
    float s = 0.0f;
    for (int b = threadIdx.x; b < BB; b += 256)
        s += logf(g_S2[b] + g_corr[b]) - g_mlab[b];
    red[threadIdx.x] = s;
    __syncthreads();
    for (int o = 128; o; o >>= 1) {
        if (threadIdx.x < o) red[threadIdx.x] += red[threadIdx.x + o];
        __syncthreads();
    }
    if (threadIdx.x == 0) {
        float loss = red[0] / (float)BB;
        out[(size_t)BB * CC] = loss;
        if (out_size - 1 != (long long)BB * CC) out[out_size - 1] = loss;
    }
}

// ---------------------------------------------------------------------------
extern "C" void kernel_launch(void* const* d_in, const int* in_sizes, int n_in,
                              void* d_out, int out_size) {
    const float* x      = (const float*)d_in[0];
    const float* W      = (const float*)d_in[1];
    const float* bias   = (const float*)d_in[2];
    const int*   labels = (const int*)  d_in[3];
    float* out = (float*)d_out;

    static bool attr_set = false;
    if (!attr_set) {
        cudaFuncSetAttribute(k_sums,  cudaFuncAttributeMaxDynamicSharedMemorySize, SMEM_BYTES);
        cudaFuncSetAttribute(k_write, cudaFuncAttributeMaxDynamicSharedMemorySize, SMEM_BYTES);
        attr_set = true;
    }

    k_zero<<<(BB + 255) / 256, 256>>>();
    k_prep_x<<<BB / 8, 256>>>(x);
    k_prep_w<<<CCP / 8, 256>>>(W);
    k_label<<<BB / 8, 256>>>(x, W, bias, labels);

    dim3 grid(CCP / TN, BB / TM);      // (391, 16)
    k_sums<<<grid, 256, SMEM_BYTES>>>(bias);
    k_write<<<grid, 256, SMEM_BYTES>>>(bias, out);

    k_loss<<<1, 256>>>(out, out_size);
}

// round 6
// speedup vs baseline: 4.1286x; 1.1777x over previous
#include <cuda_runtime.h>
#include <cuda_fp16.h>
#include <math.h>
#include <stdint.h>

#define BB 2048      // batch
#define CC 50000     // classes
#define DD 128       // latent dim
#define CCP 50048    // padded classes = 391*128

#define TM 128
#define TN 128

static __device__ __constant__ float kCosM = 0.9950041652780258f;   // cos(0.1)
static __device__ __constant__ float kSinM = 0.09983341664682815f;  // sin(0.1)
static __device__ __constant__ float kEps  = 1e-7f;
#define L2E 1.4426950408889634f

// ---- scratch (device globals; no allocations allowed) ----
__device__ __align__(128) __half g_Xh[BB * DD];
__device__ __align__(128) __half g_Wh[(size_t)CCP * DD];
__device__ float g_S1[BB];    // sum exp(wf)
__device__ float g_S2[BB];    // sum exp(20*wf) (unmargined; corrected in k_loss)
__device__ float g_mlab[BB];  // 20 * margined cosine at label
__device__ float g_corr[BB];  // exp(20*margined) - exp(20*wf_label)

// ---------------------------------------------------------------------------
#define LDSM4(R, addr) \
    asm volatile("ldmatrix.sync.aligned.m8n8.x4.shared.b16 {%0,%1,%2,%3}, [%4];" \
        : "=r"((R)[0]), "=r"((R)[1]), "=r"((R)[2]), "=r"((R)[3]) : "r"(addr))

// fp16-accumulate MMA: d,c are 2 regs of f16x2
#define MMA16816H(C, A, B) \
    asm volatile("mma.sync.aligned.m16n8k16.row.col.f16.f16.f16.f16 " \
        "{%0,%1}, {%2,%3,%4,%5}, {%6,%7}, {%0,%1};" \
        : "+r"((C)[0]), "+r"((C)[1]) \
        : "r"((A)[0]), "r"((A)[1]), "r"((A)[2]), "r"((A)[3]), \
          "r"((B)[0]), "r"((B)[1]))

__device__ __forceinline__ uint32_t smem_to_u32(const void* p) {
    uint32_t a;
    asm("{ .reg .u64 t; cvta.to.shared.u64 t, %1; cvt.u32.u64 %0, t; }" : "=r"(a) : "l"(p));
    return a;
}

__device__ __forceinline__ float ex2(float x) {
    float y;
    asm("ex2.approx.ftz.f32 %0, %1;" : "=f"(y) : "f"(x));
    return y;
}

// ---------------------------------------------------------------------------
// one warp per row: fp32 normalize, convert to fp16 (+ zero row sums)
__global__ void k_prep_x(const float* __restrict__ x) {
    int gw = (blockIdx.x * blockDim.x + threadIdx.x) >> 5;
    int lane = threadIdx.x & 31;
    if (gw >= BB) return;
    float4 v = reinterpret_cast<const float4*>(x + (size_t)gw * DD)[lane];
    float s = v.x*v.x + v.y*v.y + v.z*v.z + v.w*v.w;
    #pragma unroll
    for (int o = 16; o; o >>= 1) s += __shfl_xor_sync(0xffffffffu, s, o);
    float inv = 1.0f / fmaxf(sqrtf(s), 1e-12f);
    __half2 h01 = __floats2half2_rn(v.x * inv, v.y * inv);
    __half2 h23 = __floats2half2_rn(v.z * inv, v.w * inv);
    reinterpret_cast<uint2*>(g_Xh + (size_t)gw * DD)[lane] =
        make_uint2(*reinterpret_cast<uint32_t*>(&h01), *reinterpret_cast<uint32_t*>(&h23));
    if (lane == 0) { g_S1[gw] = 0.0f; g_S2[gw] = 0.0f; }
}

__global__ void k_prep_w(const float* __restrict__ W) {
    int gw = (blockIdx.x * blockDim.x + threadIdx.x) >> 5;
    int lane = threadIdx.x & 31;
    if (gw >= CCP) return;
    if (gw >= CC) {
        reinterpret_cast<uint2*>(g_Wh + (size_t)gw * DD)[lane] = make_uint2(0, 0);
        return;
    }
    float4 v = reinterpret_cast<const float4*>(W + (size_t)gw * DD)[lane];
    float s = v.x*v.x + v.y*v.y + v.z*v.z + v.w*v.w;
    #pragma unroll
    for (int o = 16; o; o >>= 1) s += __shfl_xor_sync(0xffffffffu, s, o);
    float inv = 1.0f / fmaxf(sqrtf(s), 1e-12f);
    __half2 h01 = __floats2half2_rn(v.x * inv, v.y * inv);
    __half2 h23 = __floats2half2_rn(v.z * inv, v.w * inv);
    reinterpret_cast<uint2*>(g_Wh + (size_t)gw * DD)[lane] =
        make_uint2(*reinterpret_cast<uint32_t*>(&h01), *reinterpret_cast<uint32_t*>(&h23));
}

// per-row label margin correction (exact fp32 recompute of label column)
__global__ void k_label(const float* __restrict__ x, const float* __restrict__ W,
                        const float* __restrict__ b, const int* __restrict__ labels) {
    int gw = (blockIdx.x * blockDim.x + threadIdx.x) >> 5;
    int lane = threadIdx.x & 31;
    if (gw >= BB) return;
    int lab = labels[gw];
    float4 xv = reinterpret_cast<const float4*>(x + (size_t)gw * DD)[lane];
    float4 wv = reinterpret_cast<const float4*>(W + (size_t)lab * DD)[lane];
    float sxx = xv.x*xv.x + xv.y*xv.y + xv.z*xv.z + xv.w*xv.w;
    float sww = wv.x*wv.x + wv.y*wv.y + wv.z*wv.z + wv.w*wv.w;
    float sxw = xv.x*wv.x + xv.y*wv.y + xv.z*wv.z + xv.w*wv.w;
    #pragma unroll
    for (int o = 16; o; o >>= 1) {
        sxx += __shfl_xor_sync(0xffffffffu, sxx, o);
        sww += __shfl_xor_sync(0xffffffffu, sww, o);
        sxw += __shfl_xor_sync(0xffffffffu, sxw, o);
    }
    if (lane == 0) {
        float wf = sxw / (fmaxf(sqrtf(sxx), 1e-12f) * fmaxf(sqrtf(sww), 1e-12f)) + b[lab];
        float t = fminf(fmaxf(wf, -1.0f + kEps), 1.0f - kEps);
        float ctm = t * kCosM - sqrtf(fmaxf(1.0f - t * t, 0.0f)) * kSinM;
        g_mlab[gw] = 20.0f * ctm;
        g_corr[gw] = ex2(20.0f * ctm * L2E) - ex2(20.0f * wf * L2E);
    }
}

// ---------------------------------------------------------------------------
// fp16-accumulate HMMA GEMM core. CTA: 128x128, K=128 resident, 256 threads,
// 8 warps (warp tile 32x64). Smem row-major [128][128] half,
// 16B-chunk XOR swizzle (chunk ^= row&7).
// ---------------------------------------------------------------------------
#define OFF_AH    0
#define OFF_BH    32768
#define OFF_BIAS  65536
#define OFF_S1    66048
#define OFF_S2    66560
#define SMEM_BYTES 67072

__device__ __forceinline__ void load_tile(const __half* __restrict__ src,
                                          int rowBase, char* dst, int tid) {
    #pragma unroll
    for (int it = 0; it < 8; it++) {
        int idx = tid + it * 256;                // 0..2047
        int row = idx >> 4, ch = idx & 15;       // 16 chunks of 16B per row
        uint4 v = reinterpret_cast<const uint4*>(src + (size_t)(rowBase + row) * DD)[ch];
        int chs = ch ^ (row & 7);
        *reinterpret_cast<uint4*>(dst + row * 256 + chs * 16) = v;
    }
}

// c[mf][nf][0] = halves (row, col lc|lc+1); c[mf][nf][1] = (row+8, ...)
__device__ __forceinline__ void gemm_core(uint32_t sbase, int wid, int lane,
                                          uint32_t c[2][8][2]) {
    #pragma unroll
    for (int mf = 0; mf < 2; mf++)
        #pragma unroll
        for (int nf = 0; nf < 8; nf++) { c[mf][nf][0] = 0u; c[mf][nf][1] = 0u; }

    const int wm = (wid & 3) * 32;
    const int wn = (wid >> 2) * 64;
    const int g = lane >> 3;
    const int r = lane & 7;
    const uint32_t rowA  = (uint32_t)(wm + (g & 1) * 8 + r);
    const uint32_t rowBq = (uint32_t)(wn + (g >> 1) * 8 + r);

    #pragma unroll
    for (int ks = 0; ks < 8; ks++) {
        uint32_t a[2][4];
        #pragma unroll
        for (int mf = 0; mf < 2; mf++) {
            uint32_t row = rowA + mf * 16;
            uint32_t chs = (uint32_t)((2 * ks + (g >> 1)) ^ r);
            LDSM4(a[mf], sbase + OFF_AH + row * 256 + chs * 16);
        }
        uint32_t b[8][2];
        #pragma unroll
        for (int q = 0; q < 4; q++) {
            uint32_t row = rowBq + q * 16;
            uint32_t chs = (uint32_t)((2 * ks + (g & 1)) ^ r);
            uint32_t t4[4];
            LDSM4(t4, sbase + OFF_BH + row * 256 + chs * 16);
            b[2*q][0] = t4[0]; b[2*q][1] = t4[1];
            b[2*q+1][0] = t4[2]; b[2*q+1][1] = t4[3];
        }
        #pragma unroll
        for (int mf = 0; mf < 2; mf++)
            #pragma unroll
            for (int nf = 0; nf < 8; nf++)
                MMA16816H(c[mf][nf], a[mf], b[nf]);
    }
}

// ---------------------------------------------------------------------------
// Pass A: GEMM -> row sums S1 (softmax denom) and S2 (CE denom). No big stores.
// sBias holds bias*log2e; OOB columns hold -1e30 so ex2() contributes 0 (no branches).
__global__ __launch_bounds__(256, 2) void k_sums(const float* __restrict__ bias) {
    extern __shared__ char smem[];
    const uint32_t sbase = smem_to_u32(smem);
    const int tid = threadIdx.x, wid = tid >> 5, lane = tid & 31;
    const int rowBase = blockIdx.y * TM, colBase = blockIdx.x * TN;
    const int wm = (wid & 3) * 32;
    const int wn = (wid >> 2) * 64;

    load_tile(g_Xh, rowBase, smem + OFF_AH, tid);
    load_tile(g_Wh, colBase, smem + OFF_BH, tid);

    float* sBias = (float*)(smem + OFF_BIAS);
    float* sS1   = (float*)(smem + OFF_S1);
    float* sS2   = (float*)(smem + OFF_S2);
    if (tid < TM) {
        int cg = colBase + tid;
        sBias[tid] = (cg < CC) ? bias[cg] * L2E : -1e30f;
        sS1[tid] = 0.0f; sS2[tid] = 0.0f;
    }
    __syncthreads();

    uint32_t c[2][8][2];
    gemm_core(sbase, wid, lane, c);

    const int qrow = lane >> 2, qcol = lane & 3;
    float s1a[2][2], s2a[2][2];
    #pragma unroll
    for (int mf = 0; mf < 2; mf++) { s1a[mf][0]=0.f; s1a[mf][1]=0.f; s2a[mf][0]=0.f; s2a[mf][1]=0.f; }

    #pragma unroll
    for (int mf = 0; mf < 2; mf++) {
        #pragma unroll
        for (int nf = 0; nf < 8; nf++) {
            const int lc = wn + nf * 8 + qcol * 2;
            const float b0 = sBias[lc], b1 = sBias[lc + 1];
            float2 f01 = __half22float2(*reinterpret_cast<__half2*>(&c[mf][nf][0]));
            float2 f23 = __half22float2(*reinterpret_cast<__half2*>(&c[mf][nf][1]));
            float t0 = fmaf(f01.x, L2E, b0);     // wf*log2e (row lr0)
            float t1 = fmaf(f01.y, L2E, b1);
            float t2 = fmaf(f23.x, L2E, b0);     // row lr1
            float t3 = fmaf(f23.y, L2E, b1);
            s1a[mf][0] += ex2(t0) + ex2(t1);
            s2a[mf][0] += ex2(20.0f * t0) + ex2(20.0f * t1);
            s1a[mf][1] += ex2(t2) + ex2(t3);
            s2a[mf][1] += ex2(20.0f * t2) + ex2(20.0f * t3);
        }
    }
    #pragma unroll
    for (int o = 1; o <= 2; o <<= 1) {
        #pragma unroll
        for (int mf = 0; mf < 2; mf++) {
            s1a[mf][0] += __shfl_xor_sync(0xffffffffu, s1a[mf][0], o);
            s1a[mf][1] += __shfl_xor_sync(0xffffffffu, s1a[mf][1], o);
            s2a[mf][0] += __shfl_xor_sync(0xffffffffu, s2a[mf][0], o);
            s2a[mf][1] += __shfl_xor_sync(0xffffffffu, s2a[mf][1], o);
        }
    }
    if (qcol == 0) {
        #pragma unroll
        for (int mf = 0; mf < 2; mf++) {
            int lr0 = wm + mf * 16 + qrow;
            atomicAdd(&sS1[lr0], s1a[mf][0]);
            atomicAdd(&sS1[lr0 + 8], s1a[mf][1]);
            atomicAdd(&sS2[lr0], s2a[mf][0]);
            atomicAdd(&sS2[lr0 + 8], s2a[mf][1]);
        }
    }
    __syncthreads();
    if (tid < TM) {
        atomicAdd(&g_S1[rowBase + tid], sS1[tid]);
        atomicAdd(&g_S2[rowBase + tid], sS2[tid]);
    }
}

// ---------------------------------------------------------------------------
// Pass B: recompute GEMM, write final normalized fp32 predictions directly.
__global__ __launch_bounds__(256, 2) void k_write(const float* __restrict__ bias,
                                                  float* __restrict__ out) {
    extern __shared__ char smem[];
    const uint32_t sbase = smem_to_u32(smem);
    const int tid = threadIdx.x, wid = tid >> 5, lane = tid & 31;
    const int rowBase = blockIdx.y * TM, colBase = blockIdx.x * TN;
    const int wm = (wid & 3) * 32;
    const int wn = (wid >> 2) * 64;

    load_tile(g_Xh, rowBase, smem + OFF_AH, tid);
    load_tile(g_Wh, colBase, smem + OFF_BH, tid);

    float* sBias = (float*)(smem + OFF_BIAS);
    float* sInv  = (float*)(smem + OFF_S1);
    if (tid < TM) {
        int cg = colBase + tid;
        sBias[tid] = (cg < CC) ? bias[cg] * L2E : -1e30f;
        sInv[tid] = 1.0f / g_S1[rowBase + tid];
    }
    __syncthreads();

    uint32_t c[2][8][2];
    gemm_core(sbase, wid, lane, c);

    const int qrow = lane >> 2, qcol = lane & 3;
    const bool full = (colBase + TN <= CC);
    #pragma unroll
    for (int mf = 0; mf < 2; mf++) {
        const int lr0 = wm + mf * 16 + qrow;
        const int lr1 = lr0 + 8;
        const float i0 = sInv[lr0], i1 = sInv[lr1];
        const size_t rb0 = (size_t)(rowBase + lr0) * CC;
        const size_t rb1 = (size_t)(rowBase + lr1) * CC;
        #pragma unroll
        for (int nf = 0; nf < 8; nf++) {
            const int lc = wn + nf * 8 + qcol * 2;
            const int gc = colBase + lc;
            const float b0 = sBias[lc], b1 = sBias[lc + 1];
            float2 f01 = __half22float2(*reinterpret_cast<__half2*>(&c[mf][nf][0]));
            float2 f23 = __half22float2(*reinterpret_cast<__half2*>(&c[mf][nf][1]));
            float p0 = ex2(fmaf(f01.x, L2E, b0)) * i0;
            float p1 = ex2(fmaf(f01.y, L2E, b1)) * i0;
            float p2 = ex2(fmaf(f23.x, L2E, b0)) * i1;
            float p3 = ex2(fmaf(f23.y, L2E, b1)) * i1;
            if (full || gc < CC) {
                *reinterpret_cast<float2*>(&out[rb0 + gc]) = make_float2(p0, p1);
                *reinterpret_cast<float2*>(&out[rb1 + gc]) = make_float2(p2, p3);
            }
        }
    }
}

// ---------------------------------------------------------------------------
__global__ void k_loss(float* __restrict__ out, int out_size) {
    __shared__ float red[256];
    float s = 0.0f;
    for (int b = threadIdx.x; b < BB; b += 256)
        s += logf(g_S2[b] + g_corr[b]) - g_mlab[b];
    red[threadIdx.x] = s;
    __syncthreads();
    for (int o = 128; o; o >>= 1) {
        if (threadIdx.x < o) red[threadIdx.x] += red[threadIdx.x + o];
        __syncthreads();
    }
    if (threadIdx.x == 0) {
        float loss = red[0] / (float)BB;
        out[(size_t)BB * CC] = loss;
        if (out_size - 1 != (long long)BB * CC) out[out_size - 1] = loss;
    }
}

// ---------------------------------------------------------------------------
extern "C" void kernel_launch(void* const* d_in, const int* in_sizes, int n_in,
                              void* d_out, int out_size) {
    const float* x      = (const float*)d_in[0];
    const float* W      = (const float*)d_in[1];
    const float* bias   = (const float*)d_in[2];
    const int*   labels = (const int*)  d_in[3];
    float* out = (float*)d_out;

    static bool attr_set = false;
    if (!attr_set) {
        cudaFuncSetAttribute(k_sums,  cudaFuncAttributeMaxDynamicSharedMemorySize, SMEM_BYTES);
        cudaFuncSetAttribute(k_write, cudaFuncAttributeMaxDynamicSharedMemorySize, SMEM_BYTES);
        attr_set = true;
    }

    k_prep_x<<<BB / 8, 256>>>(x);
    k_prep_w<<<CCP / 8, 256>>>(W);
    k_label<<<BB / 8, 256>>>(x, W, bias, labels);

    dim3 grid(CCP / TN, BB / TM);      // (391, 16)
    k_sums<<<grid, 256, SMEM_BYTES>>>(bias);
    k_write<<<grid, 256, SMEM_BYTES>>>(bias, out);

    k_loss<<<1, 256>>>(out, out_size);
}